// round 3
// baseline (speedup 1.0000x reference)
#include <cuda_runtime.h>

#define N_NODES 200000
#define C 256
#define VC 16
#define VD 3
#define M_SEG 50000

// float4 counts
#define S_SUM_F4 (M_SEG * (C / 4))            // 3,200,000
#define V_SUM_F4 (M_SEG * (VC * VD / 4))      // 600,000
#define CNT_F4   (M_SEG / 4)                  // 12,500
#define TOT_F4   (S_SUM_F4 + V_SUM_F4 + CNT_F4)

// One packed accumulator: [s_sum | v_sum | cnt], 61 MB (fits in L2 for atomics)
__device__ float4 g_acc[TOT_F4];
__device__ float  g_inv_cnt[M_SEG];
__device__ int    g_seg_is64;

// ---------------------------------------------------------------------------
// Detect whether motif_batch is int64 or int32 (JAX may silently downcast).
// If data is int32, reading it as int64 merges pairs; the high word is a
// random value in [0, 50000) which is nonzero w.p. ~1-2e-5 per sample.
// ---------------------------------------------------------------------------
__global__ void detect_k(const unsigned long long* __restrict__ p) {
    if (threadIdx.x == 0 && blockIdx.x == 0) {
        int is64 = 1;
        #pragma unroll
        for (int i = 0; i < 16; i++) {
            if ((p[i] >> 32) != 0ULL) { is64 = 0; }
        }
        g_seg_is64 = is64;
    }
}

__global__ void zero_k() {
    int idx = blockIdx.x * blockDim.x + threadIdx.x;
    if (idx < TOT_F4) g_acc[idx] = make_float4(0.f, 0.f, 0.f, 0.f);
}

__device__ __forceinline__ int get_seg(const void* segp, int node, int is64) {
    if (is64) return (int)((const long long*)segp)[node];
    return ((const int*)segp)[node];
}

__device__ __forceinline__ void red_add_v4(float* p, float4 v) {
    asm volatile("red.global.add.v4.f32 [%0], {%1,%2,%3,%4};"
                 :: "l"(p), "f"(v.x), "f"(v.y), "f"(v.z), "f"(v.w) : "memory");
}

__device__ __forceinline__ void red_add_f32(float* p, float v) {
    asm volatile("red.global.add.f32 [%0], %1;" :: "l"(p), "f"(v) : "memory");
}

// ---------------------------------------------------------------------------
// Scatter: s (N*64 float4), v (N*12 float4), counts (N). One launch.
// ---------------------------------------------------------------------------
__global__ void scatter_k(const float4* __restrict__ s4,
                          const float4* __restrict__ v4,
                          const void*   __restrict__ segp) {
    int idx = blockIdx.x * blockDim.x + threadIdx.x;
    int is64 = g_seg_is64;

    if (idx < N_NODES * (C / 4)) {
        int node = idx >> 6;
        int q    = idx & 63;
        int m    = get_seg(segp, node, is64);
        float4 val = s4[idx];
        red_add_v4((float*)&g_acc[m * 64 + q], val);
    }
    if (idx < N_NODES * (VC * VD / 4)) {
        int node = idx / 12;
        int q    = idx - node * 12;
        int m    = get_seg(segp, node, is64);
        float4 val = v4[idx];
        red_add_v4((float*)&g_acc[S_SUM_F4 + m * 12 + q], val);
    }
    if (idx < N_NODES) {
        int m = get_seg(segp, idx, is64);
        float* cnt = (float*)&g_acc[S_SUM_F4 + V_SUM_F4];
        red_add_f32(cnt + m, 1.0f);
    }
}

__global__ void inv_k() {
    int idx = blockIdx.x * blockDim.x + threadIdx.x;
    if (idx < M_SEG) {
        const float* cnt = (const float*)&g_acc[S_SUM_F4 + V_SUM_F4];
        g_inv_cnt[idx] = 1.0f / fmaxf(cnt[idx], 1.0f);
    }
}

// ---------------------------------------------------------------------------
// s_out = (s_sum * inv_cnt) @ Ws^T + bs     [50000, 256] x [256, 256]
// 64x64x16 shared tiles, 4x4 register micro-tile, 256 threads.
// ---------------------------------------------------------------------------
#define BM 64
#define BN 64
#define BK 16

__global__ void __launch_bounds__(256) finish_s_k(const float* __restrict__ Ws,
                                                  const float* __restrict__ bs,
                                                  float* __restrict__ out) {
    __shared__ float As[BK][BM + 1];
    __shared__ float Bs[BK][BN + 1];

    int tid = threadIdx.x;
    int m0 = blockIdx.x * BM;
    int n0 = blockIdx.y * BN;
    int lr = tid >> 2;     // 0..63: row within tile for loads
    int lq = tid & 3;      // which float4 within the 16-wide K slab
    int ty = tid >> 4;     // 0..15
    int tx = tid & 15;     // 0..15

    const float4* A4 = (const float4*)g_acc;       // s_sum at offset 0
    const float4* W4 = (const float4*)Ws;

    int arow = m0 + lr;
    float inv = (arow < M_SEG) ? g_inv_cnt[arow] : 0.f;

    float acc[4][4];
    #pragma unroll
    for (int i = 0; i < 4; i++)
        #pragma unroll
        for (int j = 0; j < 4; j++) acc[i][j] = 0.f;

    for (int k0 = 0; k0 < C; k0 += BK) {
        float4 a = make_float4(0.f, 0.f, 0.f, 0.f);
        if (arow < M_SEG) a = A4[arow * (C / 4) + (k0 >> 2) + lq];
        float4 b = W4[(n0 + lr) * (C / 4) + (k0 >> 2) + lq];

        int kb = lq * 4;
        As[kb + 0][lr] = a.x * inv;
        As[kb + 1][lr] = a.y * inv;
        As[kb + 2][lr] = a.z * inv;
        As[kb + 3][lr] = a.w * inv;
        Bs[kb + 0][lr] = b.x;
        Bs[kb + 1][lr] = b.y;
        Bs[kb + 2][lr] = b.z;
        Bs[kb + 3][lr] = b.w;
        __syncthreads();

        #pragma unroll
        for (int kk = 0; kk < BK; kk++) {
            float ar[4], br[4];
            #pragma unroll
            for (int i = 0; i < 4; i++) {
                ar[i] = As[kk][ty * 4 + i];
                br[i] = Bs[kk][tx * 4 + i];
            }
            #pragma unroll
            for (int i = 0; i < 4; i++)
                #pragma unroll
                for (int j = 0; j < 4; j++)
                    acc[i][j] += ar[i] * br[j];
        }
        __syncthreads();
    }

    #pragma unroll
    for (int i = 0; i < 4; i++) {
        int row = m0 + ty * 4 + i;
        if (row < M_SEG) {
            #pragma unroll
            for (int j = 0; j < 4; j++) {
                int col = n0 + tx * 4 + j;
                out[(size_t)row * C + col] = acc[i][j] + bs[col];
            }
        }
    }
}

// ---------------------------------------------------------------------------
// v_out[m,o,d] = inv_cnt[m] * sum_c v_sum[m,c,d] * Wv[o,c] + bv[o]
// Block: 256 threads = 16 motifs x 16 outputs.
// ---------------------------------------------------------------------------
__global__ void __launch_bounds__(256) finish_v_k(const float* __restrict__ Wv,
                                                  const float* __restrict__ bv,
                                                  float* __restrict__ vout) {
    __shared__ float vs[16][48];
    __shared__ float wv[16][16];
    __shared__ float bvs[16];
    __shared__ float invs[16];

    int tid = threadIdx.x;
    int mbase = blockIdx.x * 16;
    const float* vsum = (const float*)(g_acc + S_SUM_F4);

    for (int i = tid; i < 16 * 48; i += 256) {
        int mi = i / 48, q = i - mi * 48;
        vs[mi][q] = vsum[(size_t)(mbase + mi) * 48 + q];
    }
    wv[tid >> 4][tid & 15] = Wv[tid];
    if (tid < 16) {
        bvs[tid]  = bv[tid];
        invs[tid] = g_inv_cnt[mbase + tid];
    }
    __syncthreads();

    int mi = tid >> 4;
    int o  = tid & 15;
    float a0 = 0.f, a1 = 0.f, a2 = 0.f;
    #pragma unroll
    for (int c = 0; c < 16; c++) {
        float w = wv[o][c];
        a0 += vs[mi][c * 3 + 0] * w;
        a1 += vs[mi][c * 3 + 1] * w;
        a2 += vs[mi][c * 3 + 2] * w;
    }
    int m = mbase + mi;
    float inv = invs[mi];
    float b = bvs[o];
    size_t base = (size_t)m * 48 + o * 3;
    vout[base + 0] = a0 * inv + b;
    vout[base + 1] = a1 * inv + b;
    vout[base + 2] = a2 * inv + b;
}

// ---------------------------------------------------------------------------
extern "C" void kernel_launch(void* const* d_in, const int* in_sizes, int n_in,
                              void* d_out, int out_size) {
    const float4* s4  = (const float4*)d_in[0];
    const float4* v4  = (const float4*)d_in[1];
    const void*   seg = d_in[2];
    const float*  Ws  = (const float*)d_in[3];
    const float*  bs  = (const float*)d_in[4];
    const float*  Wv  = (const float*)d_in[5];
    const float*  bv  = (const float*)d_in[6];

    float* out   = (float*)d_out;
    float* s_out = out;
    float* v_out = out + (size_t)M_SEG * C;

    detect_k<<<1, 32>>>((const unsigned long long*)seg);
    zero_k<<<(TOT_F4 + 255) / 256, 256>>>();
    scatter_k<<<(N_NODES * (C / 4) + 255) / 256, 256>>>(s4, v4, seg);
    inv_k<<<(M_SEG + 255) / 256, 256>>>();

    dim3 gs((M_SEG + BM - 1) / BM, C / BN);
    finish_s_k<<<gs, 256>>>(Ws, bs, s_out);
    finish_v_k<<<M_SEG / 16, 256>>>(Wv, bv, v_out);
}

// round 8
// speedup vs baseline: 1.2326x; 1.2326x over previous
#include <cuda_runtime.h>

#define N_NODES 200000
#define C 256
#define VC 16
#define VD 3
#define M_SEG 50000

// float4 counts
#define S_SUM_F4 (M_SEG * (C / 4))            // 3,200,000
#define V_SUM_F4 (M_SEG * (VC * VD / 4))      // 600,000
#define CNT_F4   (M_SEG / 4)                  // 12,500
#define TOT_F4   (S_SUM_F4 + V_SUM_F4 + CNT_F4)

// One packed accumulator: [s_sum | v_sum | cnt], 61 MB (fits in L2 for atomics)
__device__ float4 g_acc[TOT_F4];
__device__ float  g_inv_cnt[M_SEG];
__device__ int    g_seg_is64;

// ---------------------------------------------------------------------------
// f32x2 packed-FMA helpers (sm_100+; ptxas never auto-fuses, PTX-only)
// ---------------------------------------------------------------------------
__device__ __forceinline__ unsigned long long ffma2(unsigned long long a,
                                                    unsigned long long b,
                                                    unsigned long long c) {
    unsigned long long d;
    asm("fma.rn.f32x2 %0, %1, %2, %3;" : "=l"(d) : "l"(a), "l"(b), "l"(c));
    return d;
}

__device__ __forceinline__ unsigned long long pack_dup(float x) {
    unsigned long long r;
    unsigned int b = __float_as_uint(x);
    asm("mov.b64 %0, {%1, %1};" : "=l"(r) : "r"(b));
    return r;
}

__device__ __forceinline__ void unpack2(unsigned long long p, float& lo, float& hi) {
    lo = __uint_as_float((unsigned int)p);
    hi = __uint_as_float((unsigned int)(p >> 32));
}

// ---------------------------------------------------------------------------
// Detect whether motif_batch is int64 or int32 (JAX may silently downcast).
// ---------------------------------------------------------------------------
__global__ void detect_k(const unsigned long long* __restrict__ p) {
    if (threadIdx.x == 0 && blockIdx.x == 0) {
        int is64 = 1;
        #pragma unroll
        for (int i = 0; i < 16; i++) {
            if ((p[i] >> 32) != 0ULL) { is64 = 0; }
        }
        g_seg_is64 = is64;
    }
}

__global__ void zero_k() {
    int idx = blockIdx.x * blockDim.x + threadIdx.x;
    if (idx < TOT_F4) g_acc[idx] = make_float4(0.f, 0.f, 0.f, 0.f);
}

__device__ __forceinline__ int get_seg(const void* segp, int node, int is64) {
    if (is64) return (int)((const long long*)segp)[node];
    return ((const int*)segp)[node];
}

__device__ __forceinline__ void red_add_v4(float* p, float4 v) {
    asm volatile("red.global.add.v4.f32 [%0], {%1,%2,%3,%4};"
                 :: "l"(p), "f"(v.x), "f"(v.y), "f"(v.z), "f"(v.w) : "memory");
}

__device__ __forceinline__ void red_add_f32(float* p, float v) {
    asm volatile("red.global.add.f32 [%0], %1;" :: "l"(p), "f"(v) : "memory");
}

// ---------------------------------------------------------------------------
// Scatter: s (N*64 float4), v (N*12 float4), counts (N). One launch.
// ---------------------------------------------------------------------------
__global__ void scatter_k(const float4* __restrict__ s4,
                          const float4* __restrict__ v4,
                          const void*   __restrict__ segp) {
    int idx = blockIdx.x * blockDim.x + threadIdx.x;
    int is64 = g_seg_is64;

    if (idx < N_NODES * (C / 4)) {
        int node = idx >> 6;
        int q    = idx & 63;
        int m    = get_seg(segp, node, is64);
        float4 val = s4[idx];
        red_add_v4((float*)&g_acc[m * 64 + q], val);
    }
    if (idx < N_NODES * (VC * VD / 4)) {
        int node = idx / 12;
        int q    = idx - node * 12;
        int m    = get_seg(segp, node, is64);
        float4 val = v4[idx];
        red_add_v4((float*)&g_acc[S_SUM_F4 + m * 12 + q], val);
    }
    if (idx < N_NODES) {
        int m = get_seg(segp, idx, is64);
        float* cnt = (float*)&g_acc[S_SUM_F4 + V_SUM_F4];
        red_add_f32(cnt + m, 1.0f);
    }
}

__global__ void inv_k() {
    int idx = blockIdx.x * blockDim.x + threadIdx.x;
    if (idx < M_SEG) {
        const float* cnt = (const float*)&g_acc[S_SUM_F4 + V_SUM_F4];
        g_inv_cnt[idx] = 1.0f / fmaxf(cnt[idx], 1.0f);
    }
}

// ---------------------------------------------------------------------------
// s_out = (s_sum * inv_cnt) @ Ws^T + bs     [50000, 256] x [256, 256]
// 256x64x16 tiles, 256 threads, 16Mx4N micro-tile, f32x2-packed accumulators
// (packed along M; M-pairs are adjacent in As -> free via LDS.128).
// Per k-step: 32 FFMA2 (64 FMAs) + 4 LDS.128 A + 1 LDS.128 B + 4 MOV-dup.
// ---------------------------------------------------------------------------
#define BM 256
#define BN 64
#define BK 16
#define BS_PAD 68   // Bs row stride (floats); 68*4=272 bytes, 16B-aligned, debanked

__global__ void __launch_bounds__(256, 2) finish_s_k(const float* __restrict__ Ws,
                                                     const float* __restrict__ bs,
                                                     float* __restrict__ out) {
    __shared__ float As[BK * BM];        // As[k][m], m contiguous
    __shared__ float Bs[BK * BS_PAD];    // Bs[k][n], n contiguous (padded)

    int t  = threadIdx.x;
    int m0 = blockIdx.x * BM;
    int n0 = blockIdx.y * BN;
    int tx = t & 15;          // N group: cols n0 + tx*4 .. +3
    int ty = t >> 4;          // M group: rows m0 + ty*16 .. +15
    int bn = t >> 2;          // B load: row of Ws (0..63)
    int bk = t & 3;           // B load: which float4 of the K slab

    const float4* A4 = (const float4*)g_acc;   // s_sum at offset 0
    const float4* W4 = (const float4*)Ws;

    int   ar  = m0 + t;                        // the A row this thread stages
    float inv = (ar < M_SEG) ? g_inv_cnt[ar] : 0.f;

    unsigned long long acc[8][4];              // 8 M-pairs x 4 N
    #pragma unroll
    for (int i = 0; i < 8; i++)
        #pragma unroll
        for (int j = 0; j < 4; j++) acc[i][j] = 0ULL;

    for (int k0 = 0; k0 < C; k0 += BK) {
        // stage global loads before the barrier
        float4 av[4];
        #pragma unroll
        for (int q = 0; q < 4; q++) {
            av[q] = (ar < M_SEG) ? A4[(size_t)ar * (C / 4) + (k0 >> 2) + q]
                                 : make_float4(0.f, 0.f, 0.f, 0.f);
        }
        float4 wv = W4[(size_t)(n0 + bn) * (C / 4) + (k0 >> 2) + bk];

        __syncthreads();   // previous iteration's reads complete

        // As[k][m] transpose-store (m = t: warp-consecutive -> conflict-free)
        #pragma unroll
        for (int q = 0; q < 4; q++) {
            As[(q * 4 + 0) * BM + t] = av[q].x * inv;
            As[(q * 4 + 1) * BM + t] = av[q].y * inv;
            As[(q * 4 + 2) * BM + t] = av[q].z * inv;
            As[(q * 4 + 3) * BM + t] = av[q].w * inv;
        }
        // Bs[k][n] = Ws[n][k]
        Bs[(bk * 4 + 0) * BS_PAD + bn] = wv.x;
        Bs[(bk * 4 + 1) * BS_PAD + bn] = wv.y;
        Bs[(bk * 4 + 2) * BS_PAD + bn] = wv.z;
        Bs[(bk * 4 + 3) * BS_PAD + bn] = wv.w;
        __syncthreads();

        #pragma unroll
        for (int kk = 0; kk < BK; kk++) {
            // 16 M values = 8 natural f32x2 pairs, via 4x LDS.128 (broadcast)
            const ulonglong2* ap = (const ulonglong2*)&As[kk * BM + ty * 16];
            ulonglong2 p0 = ap[0], p1 = ap[1], p2 = ap[2], p3 = ap[3];
            unsigned long long a[8] = {p0.x, p0.y, p1.x, p1.y,
                                       p2.x, p2.y, p3.x, p3.y};
            // 4 N values, one LDS.128, then register-dup
            float4 bv = *(const float4*)&Bs[kk * BS_PAD + tx * 4];
            unsigned long long bd[4] = {pack_dup(bv.x), pack_dup(bv.y),
                                        pack_dup(bv.z), pack_dup(bv.w)};
            #pragma unroll
            for (int i = 0; i < 8; i++)
                #pragma unroll
                for (int j = 0; j < 4; j++)
                    acc[i][j] = ffma2(a[i], bd[j], acc[i][j]);
        }
    }

    // epilogue: unpack, add bias, vector store
    float4 bsv = *(const float4*)&bs[n0 + tx * 4];
    #pragma unroll
    for (int i = 0; i < 8; i++) {
        int r0 = m0 + ty * 16 + 2 * i;
        float lo0, hi0, lo1, hi1, lo2, hi2, lo3, hi3;
        unpack2(acc[i][0], lo0, hi0);
        unpack2(acc[i][1], lo1, hi1);
        unpack2(acc[i][2], lo2, hi2);
        unpack2(acc[i][3], lo3, hi3);
        if (r0 < M_SEG) {
            float4 o = make_float4(lo0 + bsv.x, lo1 + bsv.y,
                                   lo2 + bsv.z, lo3 + bsv.w);
            *(float4*)&out[(size_t)r0 * C + n0 + tx * 4] = o;
        }
        if (r0 + 1 < M_SEG) {
            float4 o = make_float4(hi0 + bsv.x, hi1 + bsv.y,
                                   hi2 + bsv.z, hi3 + bsv.w);
            *(float4*)&out[(size_t)(r0 + 1) * C + n0 + tx * 4] = o;
        }
    }
}

// ---------------------------------------------------------------------------
// v_out[m,o,d] = inv_cnt[m] * sum_c v_sum[m,c,d] * Wv[o,c] + bv[o]
// ---------------------------------------------------------------------------
__global__ void __launch_bounds__(256) finish_v_k(const float* __restrict__ Wv,
                                                  const float* __restrict__ bv,
                                                  float* __restrict__ vout) {
    __shared__ float vs[16][48];
    __shared__ float wv[16][16];
    __shared__ float bvs[16];
    __shared__ float invs[16];

    int tid = threadIdx.x;
    int mbase = blockIdx.x * 16;
    const float* vsum = (const float*)(g_acc + S_SUM_F4);

    for (int i = tid; i < 16 * 48; i += 256) {
        int mi = i / 48, q = i - mi * 48;
        vs[mi][q] = vsum[(size_t)(mbase + mi) * 48 + q];
    }
    wv[tid >> 4][tid & 15] = Wv[tid];
    if (tid < 16) {
        bvs[tid]  = bv[tid];
        invs[tid] = g_inv_cnt[mbase + tid];
    }
    __syncthreads();

    int mi = tid >> 4;
    int o  = tid & 15;
    float a0 = 0.f, a1 = 0.f, a2 = 0.f;
    #pragma unroll
    for (int c = 0; c < 16; c++) {
        float w = wv[o][c];
        a0 += vs[mi][c * 3 + 0] * w;
        a1 += vs[mi][c * 3 + 1] * w;
        a2 += vs[mi][c * 3 + 2] * w;
    }
    int m = mbase + mi;
    float inv = invs[mi];
    float b = bvs[o];
    size_t base = (size_t)m * 48 + o * 3;
    vout[base + 0] = a0 * inv + b;
    vout[base + 1] = a1 * inv + b;
    vout[base + 2] = a2 * inv + b;
}

// ---------------------------------------------------------------------------
extern "C" void kernel_launch(void* const* d_in, const int* in_sizes, int n_in,
                              void* d_out, int out_size) {
    const float4* s4  = (const float4*)d_in[0];
    const float4* v4  = (const float4*)d_in[1];
    const void*   seg = d_in[2];
    const float*  Ws  = (const float*)d_in[3];
    const float*  bs  = (const float*)d_in[4];
    const float*  Wv  = (const float*)d_in[5];
    const float*  bv  = (const float*)d_in[6];

    float* out   = (float*)d_out;
    float* s_out = out;
    float* v_out = out + (size_t)M_SEG * C;

    detect_k<<<1, 32>>>((const unsigned long long*)seg);
    zero_k<<<(TOT_F4 + 255) / 256, 256>>>();
    scatter_k<<<(N_NODES * (C / 4) + 255) / 256, 256>>>(s4, v4, seg);
    inv_k<<<(M_SEG + 255) / 256, 256>>>();

    dim3 gs((M_SEG + BM - 1) / BM, C / BN);
    finish_s_k<<<gs, 256>>>(Ws, bs, s_out);
    finish_v_k<<<M_SEG / 16, 256>>>(Wv, bv, v_out);
}